// round 17
// baseline (speedup 1.0000x reference)
#include <cuda_runtime.h>
#include <math.h>

#define FDIM 128
#define GMAX 50000
#define CAP  192
#define OVF_MAX 4096

// ---------------- device scratch (zero-initialized .bss; self-restoring) ----------------
__device__ int g_cnt[GMAX];                 // per-segment node count (restored to 0 by pool)
__device__ int g_perm[(size_t)GMAX * CAP];  // bucketed node indices
__device__ int g_ovf[OVF_MAX];              // overflow node list (normally empty)
__device__ int g_novf;                      // overflow count (reset by pool's last block)
__device__ int g_is64;                      // seg dtype flag (written by scatter)
__device__ int g_done;                      // block-arrival ticket (reset by last block)

__device__ __forceinline__ float tanh_fast(float x) {
    float r;
    asm("tanh.approx.f32 %0, %1;" : "=f"(r) : "f"(x));
    return r;
}

__device__ __forceinline__ void facc(float4& a, const float4& v) {
    a.x += v.x; a.y += v.y; a.z += v.z; a.w += v.w;
}

// ---------------- kernel 1: scatter nodes into per-segment buckets (1 node/thread) ----------------
__global__ void __launch_bounds__(256) scatter_kernel(const void* __restrict__ seg, int N) {
    __shared__ int s_is64;
    if (threadIdx.x == 0) {
        // int64 ids < 2^32 have zero high words; 64 random int32 ids all-zero: p ~ 0
        const unsigned int* w = (const unsigned int*)seg;
        unsigned int acc = 0;
        #pragma unroll
        for (int k = 0; k < 64; k++) acc |= w[2 * k + 1];
        s_is64 = (acc == 0u) ? 1 : 0;
        if (blockIdx.x == 0) g_is64 = s_is64;
    }
    __syncthreads();

    const int i = blockIdx.x * blockDim.x + threadIdx.x;
    if (i >= N) return;
    const int s = s_is64 ? (int)((const long long*)seg)[i]
                         : ((const int*)seg)[i];
    int slot = atomicAdd(&g_cnt[s], 1);
    if (slot < CAP) {
        g_perm[(size_t)s * CAP + slot] = i;
    } else {
        int o = atomicAdd(&g_novf, 1);
        if (o < OVF_MAX) g_ovf[o] = i;
    }
}

// ---------------- kernel 2: persistent fused gather-pool + per-warp MLP ----------------
// Single wave of blocks; each warp strides over segments (g += gridDim.x*8).
// Gather: 4 rows/iter with the NEXT int4 index prefetched. Epilogue: per-warp
// GEMV from L1-hot W1, tanh.approx, warp-reduced dot. No cross-warp coupling.
__global__ void __launch_bounds__(256) pool_mlp_kernel(
    const float* __restrict__ h,
    const void*  __restrict__ seg,
    const float* __restrict__ W1,   // [128,128] row-major: W1[k][c]
    const float* __restrict__ b1,   // [128]
    const float* __restrict__ W2,   // [128]
    const float* __restrict__ b2,   // [1]
    float* __restrict__ y, int G)
{
    __shared__ float sp[8][FDIM];               // pooled row per warp (4 KB)
    const int warp = threadIdx.x >> 5;
    const int lane = threadIdx.x & 31;
    const int nov = g_novf;                     // read before any block resets it
    const int stride = gridDim.x * 8;

    for (int g = blockIdx.x * 8 + warp; g < G; g += stride) {
        const int n = g_cnt[g];
        if (lane == 0) g_cnt[g] = 0;            // self-restore for next replay
        const int nn = min(n, CAP);
        const int* pm = &g_perm[(size_t)g * CAP];

        float4 a0 = make_float4(0.f, 0.f, 0.f, 0.f);
        float4 a1 = a0;

        // 4-row batches, index vector prefetched one iteration ahead
        int4 id = make_int4(0, 0, 0, 0);
        if (nn >= 4) id = __ldg((const int4*)pm);
        int i = 0;
        for (; i + 4 <= nn; i += 4) {
            int4 nx = id;
            if (i + 8 <= nn) nx = __ldg((const int4*)(pm + i + 4));
            float4 v0 = __ldcs((const float4*)(h + (size_t)id.x * FDIM) + lane);
            float4 v1 = __ldcs((const float4*)(h + (size_t)id.y * FDIM) + lane);
            float4 v2 = __ldcs((const float4*)(h + (size_t)id.z * FDIM) + lane);
            float4 v3 = __ldcs((const float4*)(h + (size_t)id.w * FDIM) + lane);
            facc(a0, v0); facc(a1, v1); facc(a0, v2); facc(a1, v3);
            id = nx;
        }
        for (; i < nn; i++) {
            int nd = __ldg(pm + i);
            float4 v = __ldcs((const float4*)(h + (size_t)nd * FDIM) + lane);
            facc(a0, v);
        }

        // overflow path (correctness safety net; empty for real data)
        if (nov > 0) {
            const int m = min(nov, OVF_MAX);
            const int is64 = g_is64;
            for (int k = 0; k < m; k++) {
                int nd = g_ovf[k];
                int s = is64 ? (int)((const long long*)seg)[nd]
                             : ((const int*)seg)[nd];
                if (s == g) {
                    float4 v = __ldcs((const float4*)(h + (size_t)nd * FDIM) + lane);
                    facc(a0, v);
                }
            }
        }

        float4 acc;
        acc.x = a0.x + a1.x; acc.y = a0.y + a1.y;
        acc.z = a0.z + a1.z; acc.w = a0.w + a1.w;
        ((float4*)sp[warp])[lane] = acc;
        __syncwarp();

        // hidden[4l..4l+3] = tanh(b1 + pooled @ W1); y = hidden . W2 + b2
        float4 bb = __ldg((const float4*)b1 + lane);
        float h0 = bb.x, h1 = bb.y, h2 = bb.z, h3 = bb.w;
        const float4* W1v = (const float4*)W1;  // row k, chunk lane
        const float* sA = sp[warp];

        #pragma unroll 4
        for (int k = 0; k < FDIM; k++) {
            float4 w = __ldg(W1v + k * 32 + lane);
            float pk = sA[k];
            h0 = fmaf(pk, w.x, h0);
            h1 = fmaf(pk, w.y, h1);
            h2 = fmaf(pk, w.z, h2);
            h3 = fmaf(pk, w.w, h3);
        }

        float4 w2 = __ldg((const float4*)W2 + lane);
        float p = tanh_fast(h0) * w2.x + tanh_fast(h1) * w2.y
                + tanh_fast(h2) * w2.z + tanh_fast(h3) * w2.w;

        #pragma unroll
        for (int off = 16; off; off >>= 1)
            p += __shfl_down_sync(0xffffffffu, p, off);
        if (lane == 0) y[g] = p + __ldg(b2);
        __syncwarp();
    }

    // ---- elected last block resets overflow state for the next replay ----
    if (threadIdx.x == 0) {
        __threadfence();
        int t = atomicAdd(&g_done, 1);
        if (t == (int)gridDim.x - 1) {
            g_novf = 0;
            g_done = 0;
        }
    }
}

// ---------------- launch ----------------
extern "C" void kernel_launch(void* const* d_in, const int* in_sizes, int n_in,
                              void* d_out, int out_size) {
    const float* h   = (const float*)d_in[0];
    const void*  seg = d_in[1];
    const int N = in_sizes[0] / FDIM;
    const int G = out_size;          // OUT = 1

    int iw = -1;
    for (int i = 2; i < n_in; i++) {
        if (in_sizes[i] == FDIM * FDIM) { iw = i; break; }
    }
    const float* W1 = (const float*)d_in[iw];
    const float* b1 = (const float*)d_in[iw + 1];
    const float* W2 = (const float*)d_in[iw + 2];
    const float* b2 = (const float*)d_in[iw + 3];
    float* y = (float*)d_out;

    scatter_kernel<<<(N + 255) / 256, 256>>>(seg, N);

    int nblk = (G + 7) / 8;
    const int wave = 148 * 5;            // one resident wave (5 blocks/SM at 44 regs)
    if (nblk > wave) nblk = wave;
    pool_mlp_kernel<<<nblk, 256>>>(h, seg, W1, b1, W2, b2, y, G);
}